// round 15
// baseline (speedup 1.0000x reference)
#include <cuda_runtime.h>
#include <cuda_bf16.h>
#include <cuda_pipeline.h>
#include <cstdint>

// AttentionRouting: u [B=4, I=32, N=32, J=16, H=32, W=32] f32, bias [1,32,32,1,1,1]
//   v = sum_i u; c_raw = sum_j u*v; c = softmax_n(0.25*c_raw) + bias
//   s = sum_i u*c; squash over j.
//
// R15: 4-stage rolling cp.async pipelines in K1 and K3 — per j-group
// wait_prior -> barrier -> partial reduction, so 3/4 of the smem reduction
// overlaps the in-flight stream. Only K1's c-pass and K3's squash are
// exposed. K2 unchanged; K3 keeps reversed (b,n) for L2 tail reuse.

#define BB 4
#define II 32
#define NN 32
#define JJ 16
#define HH 32
#define WW 32
#define HW 1024
#define STRIDE_I 524288   // N*J*H*W

// scratch: c_raw [B,I,N,H,W] 16MB, lse [B,I,H,W] 512KB
__device__ float g_craw[BB * II * NN * HW];
__device__ float g_lse[BB * II * HW];

// ---------------------------------------------------------------------------
// K1: CTA = (b,n,h). 256 threads. Dynamic smem u_s 64KB + static vph 4KB.
// ---------------------------------------------------------------------------
__global__ void __launch_bounds__(256) k1_craw(const float* __restrict__ u) {
    extern __shared__ float u_s[];                 // [i*512 + j*32 + w]
    __shared__ float vph[JJ][2][WW];               // [j][ih][w] 4 KB

    const int bid = blockIdx.x;                    // (b*NN + n)*HH + h
    const int h = bid & 31;
    const int n = (bid >> 5) & 31;
    const int b = bid >> 10;
    const int tid = threadIdx.x;
    const int lane = tid & 31;

    // ---- issue 4 commit-groups of 4 j's each ----
    {
        const int i = tid >> 3;
        const int q = tid & 7;
        const float* up = u + ((size_t)((b * II + i) * NN + n)) * (JJ * HW)
                            + h * WW + q * 4;
        float* dst = u_s + i * 512 + q * 4;
#pragma unroll
        for (int g = 0; g < 4; g++) {
#pragma unroll
            for (int jj = 0; jj < 4; jj++) {
                const int j = g * 4 + jj;
                __pipeline_memcpy_async(dst + j * 32, up + j * HW, 16);
            }
            __pipeline_commit();
        }
    }

    // ---- rolling v-partials: group g while g+1.. stream ----
    const int jl = (tid >> 6) & 3;                 // 0..3
    const int ih = (tid >> 5) & 1;                 // i half
#pragma unroll
    for (int g = 0; g < 4; g++) {
        __pipeline_wait_prior(3 - g);
        __syncthreads();
        const int j = g * 4 + jl;
        const int ibase = ih * 16;
        float a0 = 0.f, a1 = 0.f, a2 = 0.f, a3 = 0.f;
#pragma unroll
        for (int ii = 0; ii < 16; ii += 4) {
            a0 += u_s[(ibase + ii + 0) * 512 + j * 32 + lane];
            a1 += u_s[(ibase + ii + 1) * 512 + j * 32 + lane];
            a2 += u_s[(ibase + ii + 2) * 512 + j * 32 + lane];
            a3 += u_s[(ibase + ii + 3) * 512 + j * 32 + lane];
        }
        vph[j][ih][lane] = (a0 + a1) + (a2 + a3);
    }
    __syncthreads();

    // ---- c-pass: c_raw[i][w] = sum_j u_s[i][j][w] * v[j][w] ----
    {
        float vreg[JJ];
#pragma unroll
        for (int j = 0; j < JJ; j++)
            vreg[j] = vph[j][0][lane] + vph[j][1][lane];

        const int i0 = tid >> 5;                   // 0..7
#pragma unroll
        for (int m = 0; m < 4; m++) {
            const int i = i0 + 8 * m;
            float a0 = 0.f, a1 = 0.f;
#pragma unroll
            for (int j = 0; j < JJ; j += 2) {
                a0 += u_s[i * 512 + (j + 0) * 32 + lane] * vreg[j + 0];
                a1 += u_s[i * 512 + (j + 1) * 32 + lane] * vreg[j + 1];
            }
            g_craw[((size_t)((b * II + i) * NN + n)) * HW + h * WW + lane] =
                a0 + a1;
        }
    }
}

// ---------------------------------------------------------------------------
// K2: per-pixel (b,i,h,w) log-sum-exp over n of 0.25*c_raw.
// ---------------------------------------------------------------------------
__global__ void __launch_bounds__(256) k2_lse() {
    const int t = blockIdx.x * 256 + threadIdx.x;  // 0..131071
    const int hw = t & 1023;
    const int bi = t >> 10;                        // b*II + i
    const float* p = g_craw + bi * (NN * HW) + hw;

    float vals[NN];
    float m = -3.402823466e+38f;
#pragma unroll
    for (int n = 0; n < NN; n++) {
        vals[n] = 0.25f * p[n * HW];
        m = fmaxf(m, vals[n]);
    }
    float s = 0.f;
#pragma unroll
    for (int n = 0; n < NN; n++) s += expf(vals[n] - m);
    g_lse[t] = m + logf(s);
}

// ---------------------------------------------------------------------------
// K3: CTA = (b,n,h) reversed, 256 threads. cp.async in 4 groups; c_s
// prologue overlaps stream; per-group s-partials; squash; store.
// Dynamic smem: u 64KB + c 4KB + sp 4KB = 73728 B.
// ---------------------------------------------------------------------------
__global__ void __launch_bounds__(256) k3_out(const float* __restrict__ u,
                                             const float* __restrict__ bias,
                                             float* __restrict__ out) {
    extern __shared__ float sm[];
    float* u_s = sm;                               // [i*512 + j*32 + w]
    float* c_s = sm + 16384;                       // [i*32 + w]
    float* sp  = sm + 17408;                       // [j][ih][w] = [j*64+ih*32+w]

    const int bid = blockIdx.x;                    // reversed mapping
    const int h = bid & 31;
    const int n = 31 - ((bid >> 5) & 31);
    const int b = (BB - 1) - (bid >> 10);
    const int tid = threadIdx.x;
    const int lane = tid & 31;

    // ---- issue 4 commit-groups of 4 j's each ----
    {
        const int i = tid >> 3;
        const int q = tid & 7;
        const float* up = u + ((size_t)((b * II + i) * NN + n)) * (JJ * HW)
                            + h * WW + q * 4;
        float* dst = u_s + i * 512 + q * 4;
#pragma unroll
        for (int g = 0; g < 4; g++) {
#pragma unroll
            for (int jj = 0; jj < 4; jj++) {
                const int j = g * 4 + jj;
                __pipeline_memcpy_async(dst + j * 32, up + j * HW, 16);
            }
            __pipeline_commit();
        }
    }

    // ---- c_s prologue during the stream ----
    {
        const int i0 = tid >> 5;                   // 0..7
        const int hw = h * WW + lane;
#pragma unroll
        for (int m = 0; m < 4; m++) {
            const int i = i0 + 8 * m;
            const float cr = g_craw[((size_t)((b * II + i) * NN + n)) * HW + hw];
            const float lse = g_lse[(b * II + i) * HW + hw];
            c_s[i * 32 + lane] = expf(0.25f * cr - lse)
                                 + __ldg(&bias[i * NN + n]);
        }
    }
    __syncthreads();                               // c_s visible to all

    // thread holds its 16 c-values (ih half) in registers
    const int jl = (tid >> 6) & 3;                 // 0..3
    const int ih = (tid >> 5) & 1;
    float creg[16];
#pragma unroll
    for (int ii = 0; ii < 16; ii++)
        creg[ii] = c_s[(ih * 16 + ii) * 32 + lane];

    // ---- rolling s-partials: group g while g+1.. stream ----
#pragma unroll
    for (int g = 0; g < 4; g++) {
        __pipeline_wait_prior(3 - g);
        __syncthreads();
        const int j = g * 4 + jl;
        const int ibase = ih * 16;
        float a0 = 0.f, a1 = 0.f, a2 = 0.f, a3 = 0.f;
#pragma unroll
        for (int ii = 0; ii < 16; ii += 4) {
            a0 += u_s[(ibase + ii + 0) * 512 + j * 32 + lane] * creg[ii + 0];
            a1 += u_s[(ibase + ii + 1) * 512 + j * 32 + lane] * creg[ii + 1];
            a2 += u_s[(ibase + ii + 2) * 512 + j * 32 + lane] * creg[ii + 2];
            a3 += u_s[(ibase + ii + 3) * 512 + j * 32 + lane] * creg[ii + 3];
        }
        sp[j * 64 + ih * 32 + lane] = (a0 + a1) + (a2 + a3);
    }
    __syncthreads();

    // ---- squash over j, store (thread jj = tid>>5 handles j = jj, jj+8) ----
    {
        const int jj = tid >> 5;                   // 0..7
        float sv[JJ];
        float nrm2 = 0.f;
#pragma unroll
        for (int j2 = 0; j2 < JJ; j2++) {
            const float x = sp[j2 * 64 + lane] + sp[j2 * 64 + 32 + lane];
            sv[j2] = x;
            nrm2 += x * x;
        }
        const float nrm = sqrtf(nrm2);
        const float factor =
            (1.0f - 1.0f / (expf(nrm) + 1e-20f)) / (nrm + 1e-20f);

        out[((size_t)(b * NN + n) * JJ + jj) * HW + h * WW + lane] =
            sv[jj] * factor;
        out[((size_t)(b * NN + n) * JJ + jj + 8) * HW + h * WW + lane] =
            sv[jj + 8] * factor;
    }
}

// ---------------------------------------------------------------------------
extern "C" void kernel_launch(void* const* d_in, const int* in_sizes, int n_in,
                              void* d_out, int out_size) {
    const float* u = (const float*)d_in[0];
    const float* bias = (const float*)d_in[1];
    float* out = (float*)d_out;

    cudaFuncSetAttribute(k1_craw, cudaFuncAttributeMaxDynamicSharedMemorySize,
                         II * JJ * WW * (int)sizeof(float));     // 65536 B
    cudaFuncSetAttribute(k3_out, cudaFuncAttributeMaxDynamicSharedMemorySize,
                         18432 * (int)sizeof(float));            // 73728 B

    k1_craw<<<BB * NN * HH, 256, II * JJ * WW * sizeof(float)>>>(u);
    k2_lse<<<(BB * II * HW) / 256, 256>>>();       // 512 CTAs
    k3_out<<<BB * NN * HH, 256, 18432 * sizeof(float)>>>(u, bias, out);
}

// round 16
// speedup vs baseline: 1.0368x; 1.0368x over previous
#include <cuda_runtime.h>
#include <cuda_bf16.h>
#include <cuda_pipeline.h>
#include <cstdint>

// AttentionRouting: u [B=4, I=32, N=32, J=16, H=32, W=32] f32, bias [1,32,32,1,1,1]
//   v = sum_i u; c_raw = sum_j u*v; c = softmax_n(0.25*c_raw) + bias
//   s = sum_i u*c; squash over j.
//
// R16: R14 topology (best, 89.7) with 512-thread K1/K3 — same cp.async
// stream per CTA (4096 copies, 3 CTAs/SM) but compute phases halved in
// critical path. K3 reads c from smem in the s-pass to keep regs ~32.
// K2 unchanged; K3 keeps reversed (b,n) for L2 tail reuse.

#define BB 4
#define II 32
#define NN 32
#define JJ 16
#define HH 32
#define WW 32
#define HW 1024
#define STRIDE_I 524288   // N*J*H*W

// scratch: c_raw [B,I,N,H,W] 16MB, lse [B,I,H,W] 512KB
__device__ float g_craw[BB * II * NN * HW];
__device__ float g_lse[BB * II * HW];

// ---------------------------------------------------------------------------
// K1: CTA = (b,n,h). 512 threads. Dynamic smem u_s 64KB + static v_s 2KB.
// ---------------------------------------------------------------------------
__global__ void __launch_bounds__(512) k1_craw(const float* __restrict__ u) {
    extern __shared__ float u_s[];                 // [i*512 + j*32 + w]
    __shared__ float v_s[JJ * WW];                 // 2 KB

    const int bid = blockIdx.x;                    // (b*NN + n)*HH + h
    const int h = bid & 31;
    const int n = (bid >> 5) & 31;
    const int b = bid >> 10;
    const int tid = threadIdx.x;
    const int lane = tid & 31;

    // ---- cp.async: thread (i = tid>>4, jh = (tid>>3)&1, q = tid&7) ----
    {
        const int i = tid >> 4;
        const int jh = (tid >> 3) & 1;
        const int q = tid & 7;
        const float* up = u + ((size_t)((b * II + i) * NN + n)) * (JJ * HW)
                            + h * WW + q * 4;
        float* dst = u_s + i * 512 + q * 4;
#pragma unroll
        for (int jj = 0; jj < 8; jj++) {
            const int j = jh * 8 + jj;
            __pipeline_memcpy_async(dst + j * 32, up + j * HW, 16);
        }
        __pipeline_commit();
        __pipeline_wait_prior(0);
    }
    __syncthreads();

    // ---- v-pass: thread (j = tid>>5, w) sums 32 i's ----
    {
        const int j = tid >> 5;                    // 0..15
        float a0 = 0.f, a1 = 0.f, a2 = 0.f, a3 = 0.f;
#pragma unroll
        for (int i2 = 0; i2 < II; i2 += 4) {
            a0 += u_s[(i2 + 0) * 512 + j * 32 + lane];
            a1 += u_s[(i2 + 1) * 512 + j * 32 + lane];
            a2 += u_s[(i2 + 2) * 512 + j * 32 + lane];
            a3 += u_s[(i2 + 3) * 512 + j * 32 + lane];
        }
        v_s[j * 32 + lane] = (a0 + a1) + (a2 + a3);
    }
    __syncthreads();

    // ---- c-pass: thread (i0 = tid>>5, w) handles 2 i's ----
    {
        float vreg[JJ];
#pragma unroll
        for (int j = 0; j < JJ; j++) vreg[j] = v_s[j * 32 + lane];

        const int i0 = tid >> 5;                   // 0..15
#pragma unroll
        for (int m = 0; m < 2; m++) {
            const int i = i0 + 16 * m;
            float a0 = 0.f, a1 = 0.f;
#pragma unroll
            for (int j = 0; j < JJ; j += 2) {
                a0 += u_s[i * 512 + (j + 0) * 32 + lane] * vreg[j + 0];
                a1 += u_s[i * 512 + (j + 1) * 32 + lane] * vreg[j + 1];
            }
            g_craw[((size_t)((b * II + i) * NN + n)) * HW + h * WW + lane] =
                a0 + a1;
        }
    }
}

// ---------------------------------------------------------------------------
// K2: per-pixel (b,i,h,w) log-sum-exp over n of 0.25*c_raw.
// ---------------------------------------------------------------------------
__global__ void __launch_bounds__(256) k2_lse() {
    const int t = blockIdx.x * 256 + threadIdx.x;  // 0..131071
    const int hw = t & 1023;
    const int bi = t >> 10;                        // b*II + i
    const float* p = g_craw + bi * (NN * HW) + hw;

    float vals[NN];
    float m = -3.402823466e+38f;
#pragma unroll
    for (int n = 0; n < NN; n++) {
        vals[n] = 0.25f * p[n * HW];
        m = fmaxf(m, vals[n]);
    }
    float s = 0.f;
#pragma unroll
    for (int n = 0; n < NN; n++) s += expf(vals[n] - m);
    g_lse[t] = m + logf(s);
}

// ---------------------------------------------------------------------------
// K3: CTA = (b,n,h) reversed, 512 threads. cp.async u slice overlapped with
// c_s prologue; s-pass reads c from smem; squash; store.
// Dynamic smem: u 64KB + c 4KB + s 2KB = 71680 B.
// ---------------------------------------------------------------------------
__global__ void __launch_bounds__(512) k3_out(const float* __restrict__ u,
                                             const float* __restrict__ bias,
                                             float* __restrict__ out) {
    extern __shared__ float sm[];
    float* u_s = sm;                               // [i*512 + j*32 + w]
    float* c_s = sm + 16384;                       // [i*32 + w]
    float* s_s = sm + 17408;                       // [j*32 + w]

    const int bid = blockIdx.x;                    // reversed mapping
    const int h = bid & 31;
    const int n = 31 - ((bid >> 5) & 31);
    const int b = (BB - 1) - (bid >> 10);
    const int tid = threadIdx.x;
    const int lane = tid & 31;

    // ---- cp.async u slice (fire-and-forget) ----
    {
        const int i = tid >> 4;
        const int jh = (tid >> 3) & 1;
        const int q = tid & 7;
        const float* up = u + ((size_t)((b * II + i) * NN + n)) * (JJ * HW)
                            + h * WW + q * 4;
        float* dst = u_s + i * 512 + q * 4;
#pragma unroll
        for (int jj = 0; jj < 8; jj++) {
            const int j = jh * 8 + jj;
            __pipeline_memcpy_async(dst + j * 32, up + j * HW, 16);
        }
        __pipeline_commit();
    }

    // ---- c_s prologue during the stream: thread (i0 = tid>>5, w), 2 i's ----
    {
        const int i0 = tid >> 5;                   // 0..15
        const int hw = h * WW + lane;
#pragma unroll
        for (int m = 0; m < 2; m++) {
            const int i = i0 + 16 * m;
            const float cr = g_craw[((size_t)((b * II + i) * NN + n)) * HW + hw];
            const float lse = g_lse[(b * II + i) * HW + hw];
            c_s[i * 32 + lane] = expf(0.25f * cr - lse)
                                 + __ldg(&bias[i * NN + n]);
        }
    }
    __pipeline_wait_prior(0);
    __syncthreads();

    // ---- s-pass: thread (j = tid>>5, w) sums 32 i's, c from smem ----
    const int j = tid >> 5;                        // 0..15
    float sv;
    {
        float a0 = 0.f, a1 = 0.f, a2 = 0.f, a3 = 0.f;
#pragma unroll
        for (int i = 0; i < II; i += 4) {
            a0 += u_s[(i + 0) * 512 + j * 32 + lane] * c_s[(i + 0) * 32 + lane];
            a1 += u_s[(i + 1) * 512 + j * 32 + lane] * c_s[(i + 1) * 32 + lane];
            a2 += u_s[(i + 2) * 512 + j * 32 + lane] * c_s[(i + 2) * 32 + lane];
            a3 += u_s[(i + 3) * 512 + j * 32 + lane] * c_s[(i + 3) * 32 + lane];
        }
        sv = (a0 + a1) + (a2 + a3);
        s_s[j * 32 + lane] = sv;
    }
    __syncthreads();

    // ---- squash over j, store ----
    {
        float nrm2 = 0.f;
#pragma unroll
        for (int j2 = 0; j2 < JJ; j2++) {
            const float x = s_s[j2 * 32 + lane];
            nrm2 += x * x;
        }
        const float nrm = sqrtf(nrm2);
        const float factor =
            (1.0f - 1.0f / (expf(nrm) + 1e-20f)) / (nrm + 1e-20f);

        out[((size_t)(b * NN + n) * JJ + j) * HW + h * WW + lane] =
            sv * factor;
    }
}

// ---------------------------------------------------------------------------
extern "C" void kernel_launch(void* const* d_in, const int* in_sizes, int n_in,
                              void* d_out, int out_size) {
    const float* u = (const float*)d_in[0];
    const float* bias = (const float*)d_in[1];
    float* out = (float*)d_out;

    cudaFuncSetAttribute(k1_craw, cudaFuncAttributeMaxDynamicSharedMemorySize,
                         II * JJ * WW * (int)sizeof(float));     // 65536 B
    cudaFuncSetAttribute(k3_out, cudaFuncAttributeMaxDynamicSharedMemorySize,
                         17920 * (int)sizeof(float));            // 71680 B

    k1_craw<<<BB * NN * HH, 512, II * JJ * WW * sizeof(float)>>>(u);
    k2_lse<<<(BB * II * HW) / 256, 256>>>();       // 512 CTAs
    k3_out<<<BB * NN * HH, 512, 17920 * sizeof(float)>>>(u, bias, out);
}